// round 1
// baseline (speedup 1.0000x reference)
#include <cuda_runtime.h>

#define NTOK 16384
#define EDIM 256
#define NE   8192
#define BETA 0.25f
#define LREG 0.1f
#define UW   0.1f

#define BM 128
#define BN 64
#define SPF 258   // padded float stride of shared rows
#define SPU 129   // same, in 8-byte units

typedef unsigned long long ull;

// ---------------- device scratch (no allocations allowed) ----------------
__device__ float    g_zsq[NTOK];
__device__ float    g_esq[NE];
__device__ unsigned g_dmin[NE];
__device__ unsigned g_dmax[NE];
__device__ float    g_loss_sum;
__device__ float    g_esq_sum;

__device__ __forceinline__ void ffma2(ull& d, ull a, ull b) {
    asm("fma.rn.f32x2 %0, %1, %2, %0;" : "+l"(d) : "l"(a), "l"(b));
}
__device__ __forceinline__ float lo32(ull v) { return __uint_as_float((unsigned)v); }
__device__ __forceinline__ float hi32(ull v) { return __uint_as_float((unsigned)(v >> 32)); }

// ---------------- init ----------------
__global__ void init_kernel() {
    int t = blockIdx.x * blockDim.x + threadIdx.x;
    if (t < NE) { g_dmin[t] = 0x7F800000u; g_dmax[t] = 0u; }
    if (t == 0) { g_loss_sum = 0.f; g_esq_sum = 0.f; }
}

// ---------------- row squared norms (warp per row) ----------------
__global__ void rowsq_kernel(const float* __restrict__ src, int nrows, int which) {
    int warp = threadIdx.x >> 5, lane = threadIdx.x & 31;
    int row  = blockIdx.x * 8 + warp;
    float s = 0.f;
    if (row < nrows) {
        const float* p = src + (size_t)row * EDIM;
#pragma unroll
        for (int t = 0; t < 8; ++t) { float v = p[t * 32 + lane]; s = fmaf(v, v, s); }
    }
#pragma unroll
    for (int o = 16; o; o >>= 1) s += __shfl_xor_sync(0xFFFFFFFFu, s, o);
    if (row < nrows && lane == 0) {
        if (which) g_esq[row] = s; else g_zsq[row] = s;
    }
    if (which) {
        __shared__ float ws[8];
        if (lane == 0) ws[warp] = (row < nrows) ? s : 0.f;
        __syncthreads();
        if (threadIdx.x == 0) {
            float b = 0.f;
#pragma unroll
            for (int w = 0; w < 8; ++w) b += ws[w];
            atomicAdd(&g_esq_sum, b);
        }
    }
}

// ---------------- fused GEMM + argmin + gather + loss ----------------
extern __shared__ float smem[];

__global__ __launch_bounds__(256, 1)
void argmin_kernel(const float* __restrict__ z, const float* __restrict__ emb,
                   float* __restrict__ out_zq, float* __restrict__ out_idx)
{
    float* z_sh   = smem;                       // BM*SPF
    float* e_sh   = z_sh + BM * SPF;            // BN*SPF
    float* red_s  = e_sh + BN * SPF;            // 16*128
    int*   red_i  = (int*)(red_s + 16 * 128);   // 16*128
    float* zsq_sh = (float*)(red_i + 16 * 128); // 128

    __shared__ int   fidx[BM];
    __shared__ float fl[256];

    const int tid = threadIdx.x;
    const int rg  = tid & 15;       // row group: rows rg + 16*i
    const int cg  = tid >> 4;       // col group: codes cg*4 + j
    const int row0 = blockIdx.x * BM;

    // load z tile (128 rows x 256 f32 as 8-byte pairs)
    {
        const ull* gz = (const ull*)(z + (size_t)row0 * EDIM);
        ull* z2 = (ull*)z_sh;
        for (int p = tid; p < BM * 128; p += 256) {
            int r = p >> 7, kk = p & 127;
            z2[r * SPU + kk] = gz[r * 128 + kk];
        }
    }
    if (tid < BM) zsq_sh[tid] = g_zsq[row0 + tid];

    float best[8]; int bidx[8];
#pragma unroll
    for (int i = 0; i < 8; ++i) { best[i] = 3.4e38f; bidx[i] = 0; }

    int zb[8];
#pragma unroll
    for (int i = 0; i < 8; ++i) zb[i] = (rg + 16 * i) * SPU;
    const int cb0 = (cg * 4 + 0) * SPU, cb1 = (cg * 4 + 1) * SPU;
    const int cb2 = (cg * 4 + 2) * SPU, cb3 = (cg * 4 + 3) * SPU;

    const ull* z2 = (const ull*)z_sh;
    ull* e2 = (ull*)e_sh;

    for (int jt = 0; jt < NE; jt += BN) {
        __syncthreads();
        {
            const ull* ge = (const ull*)(emb + (size_t)jt * EDIM);
            for (int p = tid; p < BN * 128; p += 256) {
                int c = p >> 7, kk = p & 127;
                e2[c * SPU + kk] = ge[c * 128 + kk];
            }
        }
        __syncthreads();

        ull acc[8][4];
#pragma unroll
        for (int i = 0; i < 8; ++i) { acc[i][0] = 0ull; acc[i][1] = 0ull; acc[i][2] = 0ull; acc[i][3] = 0ull; }

#pragma unroll 4
        for (int kk = 0; kk < 128; ++kk) {
            ull b0 = e2[cb0 + kk], b1 = e2[cb1 + kk], b2 = e2[cb2 + kk], b3 = e2[cb3 + kk];
#pragma unroll
            for (int i = 0; i < 8; ++i) {
                ull a = z2[zb[i] + kk];
                ffma2(acc[i][0], a, b0);
                ffma2(acc[i][1], a, b1);
                ffma2(acc[i][2], a, b2);
                ffma2(acc[i][3], a, b3);
            }
        }

        float eq[4];
#pragma unroll
        for (int j = 0; j < 4; ++j) eq[j] = g_esq[jt + cg * 4 + j];

#pragma unroll
        for (int i = 0; i < 8; ++i) {
            float zq = zsq_sh[rg + 16 * i];
#pragma unroll
            for (int j = 0; j < 4; ++j) {
                float dot = lo32(acc[i][j]) + hi32(acc[i][j]);
                float t   = zq + eq[j];                 // same (zsq+esq) rounding as reference
                float sc  = fmaf(-2.f, dot, t);         // == t - 2*dot, one rounding (2*dot exact)
                if (sc < best[i]) { best[i] = sc; bidx[i] = jt + cg * 4 + j; }
            }
        }
    }

    __syncthreads();
#pragma unroll
    for (int i = 0; i < 8; ++i) {
        red_s[cg * 128 + rg + 16 * i] = best[i];
        red_i[cg * 128 + rg + 16 * i] = bidx[i];
    }
    __syncthreads();

    if (tid < BM) {
        float bs = red_s[tid]; int bi = red_i[tid];
#pragma unroll
        for (int c = 1; c < 16; ++c) {
            float s = red_s[c * 128 + tid]; int ix = red_i[c * 128 + tid];
            if (s < bs || (s == bs && ix < bi)) { bs = s; bi = ix; }   // lowest-index tie-break
        }
        fidx[tid] = bi;
        if (out_idx) out_idx[row0 + tid] = (float)bi;
    }
    __syncthreads();

    // gather z_q, straight-through output, loss partial
    float ls = 0.f;
    for (int r = 0; r < BM; ++r) {
        int bi = fidx[r];
        float e  = emb[(size_t)bi * EDIM + tid];
        float zv = z_sh[r * SPF + tid];
        float t  = e - zv;                       // z_q - z
        out_zq[(size_t)(row0 + r) * EDIM + tid] = zv + t;   // z + sg(z_q - z), same roundings as ref
        ls = fmaf(t, t, ls);
    }
    fl[tid] = ls; __syncthreads();
#pragma unroll
    for (int o = 128; o; o >>= 1) { if (tid < o) fl[tid] += fl[tid + o]; __syncthreads(); }
    if (tid == 0) atomicAdd(&g_loss_sum, fl[0]);
}

// ---------------- fused GEMM + cdist min/max per row ----------------
__global__ __launch_bounds__(256, 1)
void minmax_kernel(const float* __restrict__ emb)
{
    float* z_sh    = smem;                        // BM*SPF (row slice of emb)
    float* e_sh    = z_sh + BM * SPF;             // BN*SPF
    float* red_mn  = e_sh + BN * SPF;             // 16*128
    float* red_mx  = red_mn + 16 * 128;           // 16*128
    float* esq_row = red_mx + 16 * 128;           // 128

    const int tid = threadIdx.x;
    const int rg  = tid & 15;
    const int cg  = tid >> 4;
    const int row0 = blockIdx.x * BM;
    const int j0   = blockIdx.y * (NE / 2);

    {
        const ull* gz = (const ull*)(emb + (size_t)row0 * EDIM);
        ull* z2w = (ull*)z_sh;
        for (int p = tid; p < BM * 128; p += 256) {
            int r = p >> 7, kk = p & 127;
            z2w[r * SPU + kk] = gz[r * 128 + kk];
        }
    }
    if (tid < BM) esq_row[tid] = g_esq[row0 + tid];

    float mn[8], mx[8];
#pragma unroll
    for (int i = 0; i < 8; ++i) { mn[i] = 3.4e38f; mx[i] = 0.f; }

    int zb[8];
#pragma unroll
    for (int i = 0; i < 8; ++i) zb[i] = (rg + 16 * i) * SPU;
    const int cb0 = (cg * 4 + 0) * SPU, cb1 = (cg * 4 + 1) * SPU;
    const int cb2 = (cg * 4 + 2) * SPU, cb3 = (cg * 4 + 3) * SPU;

    const ull* z2 = (const ull*)z_sh;
    ull* e2 = (ull*)e_sh;

    for (int jt = j0; jt < j0 + NE / 2; jt += BN) {
        __syncthreads();
        {
            const ull* ge = (const ull*)(emb + (size_t)jt * EDIM);
            for (int p = tid; p < BN * 128; p += 256) {
                int c = p >> 7, kk = p & 127;
                e2[c * SPU + kk] = ge[c * 128 + kk];
            }
        }
        __syncthreads();

        ull acc[8][4];
#pragma unroll
        for (int i = 0; i < 8; ++i) { acc[i][0] = 0ull; acc[i][1] = 0ull; acc[i][2] = 0ull; acc[i][3] = 0ull; }

#pragma unroll 4
        for (int kk = 0; kk < 128; ++kk) {
            ull b0 = e2[cb0 + kk], b1 = e2[cb1 + kk], b2 = e2[cb2 + kk], b3 = e2[cb3 + kk];
#pragma unroll
            for (int i = 0; i < 8; ++i) {
                ull a = z2[zb[i] + kk];
                ffma2(acc[i][0], a, b0);
                ffma2(acc[i][1], a, b1);
                ffma2(acc[i][2], a, b2);
                ffma2(acc[i][3], a, b3);
            }
        }

        float eq[4];
#pragma unroll
        for (int j = 0; j < 4; ++j) eq[j] = g_esq[jt + cg * 4 + j];

#pragma unroll
        for (int i = 0; i < 8; ++i) {
            float sqi = esq_row[rg + 16 * i];
#pragma unroll
            for (int j = 0; j < 4; ++j) {
                float dot = lo32(acc[i][j]) + hi32(acc[i][j]);
                float d2  = fmaf(-2.f, dot, sqi + eq[j]);
                d2 = fmaxf(d2, 0.f);
                float dist = (d2 > 0.f) ? sqrtf(d2) : 0.f;
                mn[i] = fminf(mn[i], dist);
                mx[i] = fmaxf(mx[i], dist);
            }
        }
    }

    __syncthreads();
#pragma unroll
    for (int i = 0; i < 8; ++i) {
        red_mn[cg * 128 + rg + 16 * i] = mn[i];
        red_mx[cg * 128 + rg + 16 * i] = mx[i];
    }
    __syncthreads();

    if (tid < BM) {
        float a = red_mn[tid], b = red_mx[tid];
#pragma unroll
        for (int c = 1; c < 16; ++c) {
            a = fminf(a, red_mn[c * 128 + tid]);
            b = fmaxf(b, red_mx[c * 128 + tid]);
        }
        atomicMin(&g_dmin[row0 + tid], __float_as_uint(a));  // valid: all values >= 0
        atomicMax(&g_dmax[row0 + tid], __float_as_uint(b));
    }
}

// ---------------- finalize scalars ----------------
__global__ void finalize_kernel(float* __restrict__ out_loss, float* __restrict__ out_qq) {
    __shared__ float sh[256];
    int tid = threadIdx.x;
    float s = 0.f;
    for (int r = tid; r < NE; r += 256)
        s += __uint_as_float(g_dmax[r]) - __uint_as_float(g_dmin[r]);
    sh[tid] = s; __syncthreads();
#pragma unroll
    for (int o = 128; o; o >>= 1) { if (tid < o) sh[tid] += sh[tid + o]; __syncthreads(); }
    if (tid == 0) {
        if (out_loss) *out_loss = (1.f + BETA) * g_loss_sum / (float)((size_t)NTOK * EDIM);
        if (out_qq)   *out_qq   = UW * (sh[0] / (float)NE) + LREG * g_esq_sum;
    }
}

// ---------------- launch ----------------
extern "C" void kernel_launch(void* const* d_in, const int* in_sizes, int n_in,
                              void* d_out, int out_size)
{
    const float* z   = (const float*)d_in[0];
    const float* emb = (const float*)d_in[1];
    if (n_in >= 2 && in_sizes[0] == NE * EDIM && in_sizes[1] == NTOK * EDIM) {
        z = (const float*)d_in[1]; emb = (const float*)d_in[0];
    }

    float* out     = (float*)d_out;
    float* out_zq  = out;
    size_t need_full = (size_t)NTOK * EDIM + NTOK + 2;
    bool   full    = ((size_t)out_size >= need_full);
    float* out_idx  = full ? out + (size_t)NTOK * EDIM : nullptr;
    float* out_loss = full ? out + (size_t)NTOK * EDIM + NTOK : nullptr;
    float* out_qq   = full ? out_loss + 1 : nullptr;

    const size_t SMEM_BYTES = (size_t)(BM * SPF + BN * SPF + 16 * 128 + 16 * 128 + 128) * 4;
    cudaFuncSetAttribute(argmin_kernel, cudaFuncAttributeMaxDynamicSharedMemorySize, (int)SMEM_BYTES);
    cudaFuncSetAttribute(minmax_kernel, cudaFuncAttributeMaxDynamicSharedMemorySize, (int)SMEM_BYTES);

    init_kernel<<<(NE + 255) / 256, 256>>>();
    rowsq_kernel<<<NTOK / 8, 256>>>(z, NTOK, 0);
    rowsq_kernel<<<NE / 8, 256>>>(emb, NE, 1);
    argmin_kernel<<<NTOK / BM, 256, SMEM_BYTES>>>(z, emb, out_zq, out_idx);
    minmax_kernel<<<dim3(NE / BM, 2), 256, SMEM_BYTES>>>(emb);
    finalize_kernel<<<1, 256>>>(out_loss, out_qq);
}

// round 2
// speedup vs baseline: 1.0011x; 1.0011x over previous
#include <cuda_runtime.h>

#define NTOK 16384
#define EDIM 256
#define NE   8192
#define BETA 0.25f
#define LREG 0.1f
#define UW   0.1f

#define BM 128
#define BN 64
#define SPF 258   // padded float stride of shared rows
#define SPU 129   // same, in 8-byte units

typedef unsigned long long ull;

// ---------------- device scratch (no allocations allowed) ----------------
__device__ float    g_zsq[NTOK];
__device__ float    g_esq[NE];
__device__ unsigned g_dmin[NE];
__device__ unsigned g_dmax[NE];
__device__ float    g_loss_sum;
__device__ float    g_esq_sum;

__device__ __forceinline__ void ffma2(ull& d, ull a, ull b) {
    asm("fma.rn.f32x2 %0, %1, %2, %0;" : "+l"(d) : "l"(a), "l"(b));
}
__device__ __forceinline__ float lo32(ull v) { return __uint_as_float((unsigned)v); }
__device__ __forceinline__ float hi32(ull v) { return __uint_as_float((unsigned)(v >> 32)); }

// ---------------- init ----------------
__global__ void init_kernel() {
    int t = blockIdx.x * blockDim.x + threadIdx.x;
    if (t < NE) { g_dmin[t] = 0x7F800000u; g_dmax[t] = 0u; }
    if (t == 0) { g_loss_sum = 0.f; g_esq_sum = 0.f; }
}

// ---------------- row squared norms (warp per row) ----------------
__global__ void rowsq_kernel(const float* __restrict__ src, int nrows, int which) {
    int warp = threadIdx.x >> 5, lane = threadIdx.x & 31;
    int row  = blockIdx.x * 8 + warp;
    float s = 0.f;
    if (row < nrows) {
        const float* p = src + (size_t)row * EDIM;
#pragma unroll
        for (int t = 0; t < 8; ++t) { float v = p[t * 32 + lane]; s = fmaf(v, v, s); }
    }
#pragma unroll
    for (int o = 16; o; o >>= 1) s += __shfl_xor_sync(0xFFFFFFFFu, s, o);
    if (row < nrows && lane == 0) {
        if (which) g_esq[row] = s; else g_zsq[row] = s;
    }
    if (which) {
        __shared__ float ws[8];
        if (lane == 0) ws[warp] = (row < nrows) ? s : 0.f;
        __syncthreads();
        if (threadIdx.x == 0) {
            float b = 0.f;
#pragma unroll
            for (int w = 0; w < 8; ++w) b += ws[w];
            atomicAdd(&g_esq_sum, b);
        }
    }
}

// ---------------- fused GEMM + argmin + gather + loss ----------------
extern __shared__ float smem[];

__global__ __launch_bounds__(256, 1)
void argmin_kernel(const float* __restrict__ z, const float* __restrict__ emb,
                   float* __restrict__ out_zq, float* __restrict__ out_idx)
{
    float* z_sh   = smem;                       // BM*SPF
    float* e_sh   = z_sh + BM * SPF;            // BN*SPF
    float* red_s  = e_sh + BN * SPF;            // 16*128
    int*   red_i  = (int*)(red_s + 16 * 128);   // 16*128
    float* zsq_sh = (float*)(red_i + 16 * 128); // 128

    __shared__ int   fidx[BM];
    __shared__ float fl[256];

    const int tid = threadIdx.x;
    const int rg  = tid & 15;       // row group: rows rg + 16*i
    const int cg  = tid >> 4;       // col group: codes cg*4 + j
    const int row0 = blockIdx.x * BM;

    // load z tile (128 rows x 256 f32 as 8-byte pairs)
    {
        const ull* gz = (const ull*)(z + (size_t)row0 * EDIM);
        ull* z2 = (ull*)z_sh;
        for (int p = tid; p < BM * 128; p += 256) {
            int r = p >> 7, kk = p & 127;
            z2[r * SPU + kk] = gz[r * 128 + kk];
        }
    }
    if (tid < BM) zsq_sh[tid] = g_zsq[row0 + tid];

    float best[8]; int bidx[8];
#pragma unroll
    for (int i = 0; i < 8; ++i) { best[i] = 3.4e38f; bidx[i] = 0; }

    int zb[8];
#pragma unroll
    for (int i = 0; i < 8; ++i) zb[i] = (rg + 16 * i) * SPU;
    const int cb0 = (cg * 4 + 0) * SPU, cb1 = (cg * 4 + 1) * SPU;
    const int cb2 = (cg * 4 + 2) * SPU, cb3 = (cg * 4 + 3) * SPU;

    const ull* z2 = (const ull*)z_sh;
    ull* e2 = (ull*)e_sh;

    for (int jt = 0; jt < NE; jt += BN) {
        __syncthreads();
        {
            const ull* ge = (const ull*)(emb + (size_t)jt * EDIM);
            for (int p = tid; p < BN * 128; p += 256) {
                int c = p >> 7, kk = p & 127;
                e2[c * SPU + kk] = ge[c * 128 + kk];
            }
        }
        __syncthreads();

        ull acc[8][4];
#pragma unroll
        for (int i = 0; i < 8; ++i) { acc[i][0] = 0ull; acc[i][1] = 0ull; acc[i][2] = 0ull; acc[i][3] = 0ull; }

#pragma unroll 4
        for (int kk = 0; kk < 128; ++kk) {
            ull b0 = e2[cb0 + kk], b1 = e2[cb1 + kk], b2 = e2[cb2 + kk], b3 = e2[cb3 + kk];
#pragma unroll
            for (int i = 0; i < 8; ++i) {
                ull a = z2[zb[i] + kk];
                ffma2(acc[i][0], a, b0);
                ffma2(acc[i][1], a, b1);
                ffma2(acc[i][2], a, b2);
                ffma2(acc[i][3], a, b3);
            }
        }

        float eq[4];
#pragma unroll
        for (int j = 0; j < 4; ++j) eq[j] = g_esq[jt + cg * 4 + j];

#pragma unroll
        for (int i = 0; i < 8; ++i) {
            float zq = zsq_sh[rg + 16 * i];
#pragma unroll
            for (int j = 0; j < 4; ++j) {
                float dot = lo32(acc[i][j]) + hi32(acc[i][j]);
                float t   = zq + eq[j];                 // same (zsq+esq) rounding as reference
                float sc  = fmaf(-2.f, dot, t);         // == t - 2*dot, one rounding (2*dot exact)
                if (sc < best[i]) { best[i] = sc; bidx[i] = jt + cg * 4 + j; }
            }
        }
    }

    __syncthreads();
#pragma unroll
    for (int i = 0; i < 8; ++i) {
        red_s[cg * 128 + rg + 16 * i] = best[i];
        red_i[cg * 128 + rg + 16 * i] = bidx[i];
    }
    __syncthreads();

    if (tid < BM) {
        float bs = red_s[tid]; int bi = red_i[tid];
#pragma unroll
        for (int c = 1; c < 16; ++c) {
            float s = red_s[c * 128 + tid]; int ix = red_i[c * 128 + tid];
            if (s < bs || (s == bs && ix < bi)) { bs = s; bi = ix; }   // lowest-index tie-break
        }
        fidx[tid] = bi;
        if (out_idx) out_idx[row0 + tid] = (float)bi;
    }
    __syncthreads();

    // gather z_q, straight-through output, loss partial
    float ls = 0.f;
    for (int r = 0; r < BM; ++r) {
        int bi = fidx[r];
        float e  = emb[(size_t)bi * EDIM + tid];
        float zv = z_sh[r * SPF + tid];
        float t  = e - zv;                       // z_q - z
        out_zq[(size_t)(row0 + r) * EDIM + tid] = zv + t;   // z + sg(z_q - z), same roundings as ref
        ls = fmaf(t, t, ls);
    }
    fl[tid] = ls; __syncthreads();
#pragma unroll
    for (int o = 128; o; o >>= 1) { if (tid < o) fl[tid] += fl[tid + o]; __syncthreads(); }
    if (tid == 0) atomicAdd(&g_loss_sum, fl[0]);
}

// ---------------- fused GEMM + cdist min/max per row ----------------
__global__ __launch_bounds__(256, 1)
void minmax_kernel(const float* __restrict__ emb)
{
    float* z_sh    = smem;                        // BM*SPF (row slice of emb)
    float* e_sh    = z_sh + BM * SPF;             // BN*SPF
    float* red_mn  = e_sh + BN * SPF;             // 16*128
    float* red_mx  = red_mn + 16 * 128;           // 16*128
    float* esq_row = red_mx + 16 * 128;           // 128

    const int tid = threadIdx.x;
    const int rg  = tid & 15;
    const int cg  = tid >> 4;
    const int row0 = blockIdx.x * BM;
    const int j0   = blockIdx.y * (NE / 2);

    {
        const ull* gz = (const ull*)(emb + (size_t)row0 * EDIM);
        ull* z2w = (ull*)z_sh;
        for (int p = tid; p < BM * 128; p += 256) {
            int r = p >> 7, kk = p & 127;
            z2w[r * SPU + kk] = gz[r * 128 + kk];
        }
    }
    if (tid < BM) esq_row[tid] = g_esq[row0 + tid];

    float mn[8], mx[8];
#pragma unroll
    for (int i = 0; i < 8; ++i) { mn[i] = 3.4e38f; mx[i] = 0.f; }

    int zb[8];
#pragma unroll
    for (int i = 0; i < 8; ++i) zb[i] = (rg + 16 * i) * SPU;
    const int cb0 = (cg * 4 + 0) * SPU, cb1 = (cg * 4 + 1) * SPU;
    const int cb2 = (cg * 4 + 2) * SPU, cb3 = (cg * 4 + 3) * SPU;

    const ull* z2 = (const ull*)z_sh;
    ull* e2 = (ull*)e_sh;

    for (int jt = j0; jt < j0 + NE / 2; jt += BN) {
        __syncthreads();
        {
            const ull* ge = (const ull*)(emb + (size_t)jt * EDIM);
            for (int p = tid; p < BN * 128; p += 256) {
                int c = p >> 7, kk = p & 127;
                e2[c * SPU + kk] = ge[c * 128 + kk];
            }
        }
        __syncthreads();

        ull acc[8][4];
#pragma unroll
        for (int i = 0; i < 8; ++i) { acc[i][0] = 0ull; acc[i][1] = 0ull; acc[i][2] = 0ull; acc[i][3] = 0ull; }

#pragma unroll 4
        for (int kk = 0; kk < 128; ++kk) {
            ull b0 = e2[cb0 + kk], b1 = e2[cb1 + kk], b2 = e2[cb2 + kk], b3 = e2[cb3 + kk];
#pragma unroll
            for (int i = 0; i < 8; ++i) {
                ull a = z2[zb[i] + kk];
                ffma2(acc[i][0], a, b0);
                ffma2(acc[i][1], a, b1);
                ffma2(acc[i][2], a, b2);
                ffma2(acc[i][3], a, b3);
            }
        }

        float eq[4];
#pragma unroll
        for (int j = 0; j < 4; ++j) eq[j] = g_esq[jt + cg * 4 + j];

#pragma unroll
        for (int i = 0; i < 8; ++i) {
            float sqi = esq_row[rg + 16 * i];
#pragma unroll
            for (int j = 0; j < 4; ++j) {
                float dot = lo32(acc[i][j]) + hi32(acc[i][j]);
                float d2  = fmaf(-2.f, dot, sqi + eq[j]);
                d2 = fmaxf(d2, 0.f);
                float dist = (d2 > 0.f) ? sqrtf(d2) : 0.f;
                mn[i] = fminf(mn[i], dist);
                mx[i] = fmaxf(mx[i], dist);
            }
        }
    }

    __syncthreads();
#pragma unroll
    for (int i = 0; i < 8; ++i) {
        red_mn[cg * 128 + rg + 16 * i] = mn[i];
        red_mx[cg * 128 + rg + 16 * i] = mx[i];
    }
    __syncthreads();

    if (tid < BM) {
        float a = red_mn[tid], b = red_mx[tid];
#pragma unroll
        for (int c = 1; c < 16; ++c) {
            a = fminf(a, red_mn[c * 128 + tid]);
            b = fmaxf(b, red_mx[c * 128 + tid]);
        }
        atomicMin(&g_dmin[row0 + tid], __float_as_uint(a));  // valid: all values >= 0
        atomicMax(&g_dmax[row0 + tid], __float_as_uint(b));
    }
}

// ---------------- finalize scalars ----------------
__global__ void finalize_kernel(float* __restrict__ out_loss, float* __restrict__ out_qq) {
    __shared__ float sh[256];
    int tid = threadIdx.x;
    float s = 0.f;
    for (int r = tid; r < NE; r += 256)
        s += __uint_as_float(g_dmax[r]) - __uint_as_float(g_dmin[r]);
    sh[tid] = s; __syncthreads();
#pragma unroll
    for (int o = 128; o; o >>= 1) { if (tid < o) sh[tid] += sh[tid + o]; __syncthreads(); }
    if (tid == 0) {
        if (out_loss) *out_loss = (1.f + BETA) * g_loss_sum / (float)((size_t)NTOK * EDIM);
        if (out_qq)   *out_qq   = UW * (sh[0] / (float)NE) + LREG * g_esq_sum;
    }
}

// ---------------- launch ----------------
extern "C" void kernel_launch(void* const* d_in, const int* in_sizes, int n_in,
                              void* d_out, int out_size)
{
    const float* z   = (const float*)d_in[0];
    const float* emb = (const float*)d_in[1];
    if (n_in >= 2 && in_sizes[0] == NE * EDIM && in_sizes[1] == NTOK * EDIM) {
        z = (const float*)d_in[1]; emb = (const float*)d_in[0];
    }

    float* out     = (float*)d_out;
    float* out_zq  = out;
    size_t need_full = (size_t)NTOK * EDIM + NTOK + 2;
    bool   full    = ((size_t)out_size >= need_full);
    float* out_idx  = full ? out + (size_t)NTOK * EDIM : nullptr;
    float* out_loss = full ? out + (size_t)NTOK * EDIM + NTOK : nullptr;
    float* out_qq   = full ? out_loss + 1 : nullptr;

    const size_t SMEM_BYTES = (size_t)(BM * SPF + BN * SPF + 16 * 128 + 16 * 128 + 128) * 4;
    cudaFuncSetAttribute(argmin_kernel, cudaFuncAttributeMaxDynamicSharedMemorySize, (int)SMEM_BYTES);
    cudaFuncSetAttribute(minmax_kernel, cudaFuncAttributeMaxDynamicSharedMemorySize, (int)SMEM_BYTES);

    init_kernel<<<(NE + 255) / 256, 256>>>();
    rowsq_kernel<<<NTOK / 8, 256>>>(z, NTOK, 0);
    rowsq_kernel<<<NE / 8, 256>>>(emb, NE, 1);
    argmin_kernel<<<NTOK / BM, 256, SMEM_BYTES>>>(z, emb, out_zq, out_idx);
    minmax_kernel<<<dim3(NE / BM, 2), 256, SMEM_BYTES>>>(emb);
    finalize_kernel<<<1, 256>>>(out_loss, out_qq);
}